// round 2
// baseline (speedup 1.0000x reference)
#include <cuda_runtime.h>
#include <math.h>

#define Bq 8
#define Sq 12
#define Nq 4096
#define Fq 4
#define Hq 64
#define CHW 68                    // F + H
#define NCOL 544                  // Bq * CHW
#define NH  (Nq*Hq)               // 262144
#define N3H (Nq*3*Hq)             // 786432
#define ZOUT ((size_t)Bq*NH)      // offset of recon in output

// -------- persistent scratch (device globals; no allocation) --------
__device__ float g_h[Bq*NH];            // hidden state [b][n*H+hc]
__device__ float g_cat[Nq*NCOL];        // GEMM rhs [k][b*68+f]
__device__ float g_a[Nq*NCOL];          // GEMM out [m][b*68+f]
__device__ float g_gate[Bq*N3H];        // sigmoid(gc1) torch-flat
__device__ float g_tconv[Bq*NH];        // tanh(gc2)

__device__ __forceinline__ float sigf(float x){ return 1.f/(1.f+expf(-x)); }

// ---- packed fp32x2 helpers (FFMA2 path, sm_100+) ----
__device__ __forceinline__ unsigned long long dup2(float v){
    unsigned long long r;
    asm("mov.b64 %0, {%1, %1};" : "=l"(r) : "f"(v));
    return r;
}
__device__ __forceinline__ void fma2(unsigned long long &d,
                                     unsigned long long a, unsigned long long b){
    asm("fma.rn.f32x2 %0, %1, %2, %0;" : "+l"(d) : "l"(a), "l"(b));
}
__device__ __forceinline__ float2 unpk(unsigned long long v){
    float2 f;
    asm("mov.b64 {%0, %1}, %2;" : "=f"(f.x), "=f"(f.y) : "l"(v));
    return f;
}

// -------- h0 = broadcast struc_emb --------
__global__ void k_init_h(const float* __restrict__ se){
    int j = blockIdx.x*256 + threadIdx.x;
    if(j < NH){
        float v = se[j];
        #pragma unroll
        for(int b=0;b<Bq;b++) g_h[(size_t)b*NH + j] = v;
    }
}

// -------- build cat[k][b*68+f] = [x_t | h] --------
__global__ void k_cat(const float* __restrict__ X, int t){
    int idx = blockIdx.x*256 + threadIdx.x;      // Nq*NCOL elements exactly
    int n = idx / NCOL, c = idx - n*NCOL;
    int b = c / CHW,  f = c - b*CHW;
    float v;
    if(f < Fq) v = X[(size_t)((b*Sq + t)*Nq + n)*Fq + f];
    else       v = g_h[(size_t)b*NH + n*Hq + (f - Fq)];
    g_cat[idx] = v;
}

// -------- SGEMM: g_a[4096,544] = adj[4096,4096] @ g_cat[4096,544] --------
// BM=256, BN=64, BK=16, 256 threads, 8x8 per-thread tile, FFMA2, double buffered.
// grid = (16, 9) = 144 blocks = one wave.
#define APAD 260
__global__ __launch_bounds__(256,1) void k_sgemm(const float* __restrict__ adj){
    __shared__ float Ash[2][16][APAD];   // [k][m]
    __shared__ float Bsh[2][16][68];     // [k][n]
    const int tid = threadIdx.x;
    const int m0 = blockIdx.x * 256;
    const int n0 = blockIdx.y * 64;
    const int tx = tid & 7;              // n group (8 cols)
    const int ty = tid >> 3;             // m group (8 rows)
    const int arow = tid >> 2;           // 0..63
    const int ak4  = (tid & 3) * 4;      // k offset 0,4,8,12
    const int brow = tid >> 4;           // 0..15 (k)
    const int bc   = (tid & 15) * 4;     // 0..60
    const bool bval = (n0 + bc) < NCOL;
    const float* aptr = adj + (size_t)(m0 + arow)*Nq + ak4;
    const float* bptr = g_cat + (size_t)brow*NCOL + n0 + bc;

    unsigned long long acc[4][8];
    #pragma unroll
    for(int p=0;p<4;p++)
        #pragma unroll
        for(int j=0;j<8;j++) acc[p][j] = 0ull;

    float4 rA[4]; float4 rB;
    #pragma unroll
    for(int r=0;r<4;r++) rA[r] = *(const float4*)(aptr + (size_t)r*64*Nq);
    rB = bval ? *(const float4*)bptr : make_float4(0.f,0.f,0.f,0.f);

    #pragma unroll
    for(int r=0;r<4;r++){
        Ash[0][ak4+0][arow+64*r] = rA[r].x; Ash[0][ak4+1][arow+64*r] = rA[r].y;
        Ash[0][ak4+2][arow+64*r] = rA[r].z; Ash[0][ak4+3][arow+64*r] = rA[r].w;
    }
    *(float4*)&Bsh[0][brow][bc] = rB;
    __syncthreads();

    #pragma unroll 1
    for(int kt=0; kt<256; kt++){
        const int buf = kt & 1;
        if(kt < 255){
            const int ko = (kt+1)*16;
            #pragma unroll
            for(int r=0;r<4;r++) rA[r] = *(const float4*)(aptr + (size_t)r*64*Nq + ko);
            rB = bval ? *(const float4*)(bptr + (size_t)ko*NCOL)
                      : make_float4(0.f,0.f,0.f,0.f);
        }
        #pragma unroll
        for(int kk=0;kk<16;kk++){
            const ulonglong2 a01 = *(const ulonglong2*)&Ash[buf][kk][ty*8];
            const ulonglong2 a23 = *(const ulonglong2*)&Ash[buf][kk][ty*8+4];
            const float4 b0 = *(const float4*)&Bsh[buf][kk][tx*8];
            const float4 b1 = *(const float4*)&Bsh[buf][kk][tx*8+4];
            unsigned long long bd[8];
            bd[0]=dup2(b0.x); bd[1]=dup2(b0.y); bd[2]=dup2(b0.z); bd[3]=dup2(b0.w);
            bd[4]=dup2(b1.x); bd[5]=dup2(b1.y); bd[6]=dup2(b1.z); bd[7]=dup2(b1.w);
            #pragma unroll
            for(int j=0;j<8;j++){
                fma2(acc[0][j], a01.x, bd[j]);
                fma2(acc[1][j], a01.y, bd[j]);
                fma2(acc[2][j], a23.x, bd[j]);
                fma2(acc[3][j], a23.y, bd[j]);
            }
        }
        __syncthreads();
        if(kt < 255){
            const int nb = buf^1;
            #pragma unroll
            for(int r=0;r<4;r++){
                Ash[nb][ak4+0][arow+64*r] = rA[r].x; Ash[nb][ak4+1][arow+64*r] = rA[r].y;
                Ash[nb][ak4+2][arow+64*r] = rA[r].z; Ash[nb][ak4+3][arow+64*r] = rA[r].w;
            }
            *(float4*)&Bsh[nb][brow][bc] = rB;
            __syncthreads();
        }
    }

    const int colbase = n0 + tx*8;
    if(colbase < NCOL){
        #pragma unroll
        for(int p=0;p<4;p++){
            float lo[8], hi[8];
            #pragma unroll
            for(int j=0;j<8;j++){ float2 u = unpk(acc[p][j]); lo[j]=u.x; hi[j]=u.y; }
            const size_t r0 = (size_t)(m0 + ty*8 + 2*p)*NCOL + colbase;
            float4 o;
            o.x=lo[0]; o.y=lo[1]; o.z=lo[2]; o.w=lo[3]; *(float4*)&g_a[r0]   = o;
            o.x=lo[4]; o.y=lo[5]; o.z=lo[6]; o.w=lo[7]; *(float4*)&g_a[r0+4] = o;
            o.x=hi[0]; o.y=hi[1]; o.z=hi[2]; o.w=hi[3]; *(float4*)&g_a[r0+NCOL]   = o;
            o.x=hi[4]; o.y=hi[5]; o.z=hi[6]; o.w=hi[7]; *(float4*)&g_a[r0+NCOL+4] = o;
        }
    }
}

// -------- per-node weight GEMM + activations (64 nodes/block, FFMA2) --------
__global__ __launch_bounds__(256,2) void k_gates(
        const float* __restrict__ W1, const float* __restrict__ b1,
        const float* __restrict__ W2, const float* __restrict__ b2){
    extern __shared__ float sm[];
    float* Wc = sm;                 // 68*256
    float* bc = Wc + 68*256;        // 256
    float* at = bc + 256;           // 68*72 (padded, [f][i])
    const int tid = threadIdx.x;
    const int b  = blockIdx.y;
    const int m0 = blockIdx.x * 64;

    for(int idx=tid; idx<68*256; idx+=256){
        int f = idx >> 8, ch = idx & 255;
        Wc[idx] = (ch < 192) ? W1[f*192 + ch] : W2[f*64 + ch - 192];
    }
    bc[tid] = (tid < 192) ? b1[tid] : b2[tid - 192];
    for(int idx=tid; idx<64*68; idx+=256){
        int i = idx / 68, f = idx - i*68;
        at[f*72 + i] = g_a[(size_t)(m0+i)*NCOL + b*CHW + f];
    }
    __syncthreads();

    const int lane = tid & 31, wg = tid >> 5;   // wg: nodes wg*8..wg*8+7
    unsigned long long acc[4][8];
    #pragma unroll
    for(int j=0;j<8;j++){
        unsigned long long bias = dup2(bc[lane + 32*j]);
        #pragma unroll
        for(int p=0;p<4;p++) acc[p][j] = bias;
    }

    #pragma unroll 4
    for(int f=0; f<68; f++){
        const ulonglong2 a01 = *(const ulonglong2*)&at[f*72 + wg*8];
        const ulonglong2 a23 = *(const ulonglong2*)&at[f*72 + wg*8 + 4];
        unsigned long long wd[8];
        #pragma unroll
        for(int j=0;j<8;j++) wd[j] = dup2(Wc[f*256 + lane + 32*j]);
        #pragma unroll
        for(int j=0;j<8;j++){
            fma2(acc[0][j], a01.x, wd[j]);
            fma2(acc[1][j], a01.y, wd[j]);
            fma2(acc[2][j], a23.x, wd[j]);
            fma2(acc[3][j], a23.y, wd[j]);
        }
    }

    #pragma unroll
    for(int p=0;p<4;p++){
        const int nlo = m0 + wg*8 + 2*p;
        #pragma unroll
        for(int j=0;j<8;j++){
            const int ch = lane + 32*j;
            float2 u = unpk(acc[p][j]);
            if(ch < 192){
                g_gate[(size_t)b*N3H + (size_t)nlo*192 + ch]       = sigf(u.x);
                g_gate[(size_t)b*N3H + (size_t)(nlo+1)*192 + ch]   = sigf(u.y);
            }else{
                g_tconv[(size_t)b*NH + (size_t)nlo*64 + (ch-192)]     = tanhf(u.x);
                g_tconv[(size_t)b*NH + (size_t)(nlo+1)*64 + (ch-192)] = tanhf(u.y);
            }
        }
    }
}

// -------- LSTM cell elementwise (torch-flat split f,i,o) --------
__global__ void k_cell(const float* __restrict__ se){
    int idx = blockIdx.x*256 + threadIdx.x;     // Bq*NH exactly
    int b = idx >> 18;                           // /NH (262144 = 2^18)
    int j = idx & (NH-1);
    const float* gg = g_gate + (size_t)b*N3H;
    float f = gg[j], i = gg[NH + j], o = gg[2*NH + j];
    float c = f*se[j] + i*g_tconv[idx];
    g_h[idx] = o * tanhf(c);
}

// -------- copy z to output --------
__global__ void k_copy_z(float* __restrict__ out){
    int idx = blockIdx.x*256 + threadIdx.x;     // Bq*NH exactly
    out[idx] = g_h[idx];
}

// -------- fused decoder: x_gates + 12-step LSTM + MLP head --------
#define WPAD 257
__global__ __launch_bounds__(256,2) void k_dec(
    const float* __restrict__ W_ih, const float* __restrict__ W_hh,
    const float* __restrict__ b_ih, const float* __restrict__ b_hh,
    const float* __restrict__ D1,   const float* __restrict__ bd1,
    const float* __restrict__ D2,   const float* __restrict__ bd2,
    float* __restrict__ out)
{
    extern __shared__ float sm[];
    float* Wsh = sm;                 // [64][257]
    float* hsh = Wsh + 64*WPAD;      // [16][64]
    float* D1s = hsh + 16*64;        // [64][32]
    const int tid = threadIdx.x, lane = tid & 31, w = tid >> 5;
    const int rA = blockIdx.x*16 + w*2;
    const int rB = rA + 1;

    for(int idx=tid; idx<256*64; idx+=256){
        int gc = idx >> 6, k = idx & 63;
        Wsh[k*WPAD + gc] = W_ih[idx];
    }
    for(int idx=tid; idx<64*32; idx+=256) D1s[idx] = D1[idx];

    float* hA = hsh + (w*2)*64;
    float* hB = hA + 64;
    hA[lane]    = g_h[(size_t)rA*64 + lane];
    hA[lane+32] = g_h[(size_t)rA*64 + lane + 32];
    hB[lane]    = g_h[(size_t)rB*64 + lane];
    hB[lane+32] = g_h[(size_t)rB*64 + lane + 32];
    __syncthreads();

    float xgA[8], xgB[8];
    #pragma unroll
    for(int i=0;i<8;i++){
        int gc = lane + 32*i;
        float bb = b_ih[gc] + b_hh[gc];
        xgA[i] = bb; xgB[i] = bb;
    }
    for(int k=0;k<64;k++){
        float ha = hA[k], hb = hB[k];
        #pragma unroll
        for(int i=0;i<8;i++){
            float wv = Wsh[k*WPAD + lane + 32*i];
            xgA[i] += ha*wv; xgB[i] += hb*wv;
        }
    }
    __syncthreads();
    for(int idx=tid; idx<256*64; idx+=256){
        int gc = idx >> 6, k = idx & 63;
        Wsh[k*WPAD + gc] = W_hh[idx];
    }
    hA[lane]=0.f; hA[lane+32]=0.f; hB[lane]=0.f; hB[lane+32]=0.f;
    float cA0=0.f, cA1=0.f, cB0=0.f, cB1=0.f;
    const float bd1r = bd1[lane];
    const float d2r  = D2[lane];
    const float bd2r = bd2[0];
    __syncthreads();

    for(int s=0; s<Sq; s++){
        float aA[8], aB[8];
        #pragma unroll
        for(int i=0;i<8;i++){ aA[i]=xgA[i]; aB[i]=xgB[i]; }
        for(int k=0;k<64;k++){
            float ha = hA[k], hb = hB[k];
            #pragma unroll
            for(int i=0;i<8;i++){
                float wv = Wsh[k*WPAD + lane + 32*i];
                aA[i] += ha*wv; aB[i] += hb*wv;
            }
        }
        float hA0,hA1,hB0,hB1;
        {
            float ig=sigf(aA[0]), fg=sigf(aA[2]), gg=tanhf(aA[4]), og=sigf(aA[6]);
            cA0 = fg*cA0 + ig*gg; hA0 = og*tanhf(cA0);
            ig=sigf(aA[1]); fg=sigf(aA[3]); gg=tanhf(aA[5]); og=sigf(aA[7]);
            cA1 = fg*cA1 + ig*gg; hA1 = og*tanhf(cA1);
            ig=sigf(aB[0]); fg=sigf(aB[2]); gg=tanhf(aB[4]); og=sigf(aB[6]);
            cB0 = fg*cB0 + ig*gg; hB0 = og*tanhf(cB0);
            ig=sigf(aB[1]); fg=sigf(aB[3]); gg=tanhf(aB[5]); og=sigf(aB[7]);
            cB1 = fg*cB1 + ig*gg; hB1 = og*tanhf(cB1);
        }
        __syncwarp();
        hA[lane]=hA0; hA[lane+32]=hA1; hB[lane]=hB0; hB[lane+32]=hB1;
        __syncwarp();

        float uA = bd1r, uB = bd1r;
        for(int k=0;k<64;k++){
            float dv = D1s[k*32 + lane];
            uA += hA[k]*dv; uB += hB[k]*dv;
        }
        uA = fmaxf(uA, 0.f)*d2r;
        uB = fmaxf(uB, 0.f)*d2r;
        #pragma unroll
        for(int off=16; off; off>>=1){
            uA += __shfl_xor_sync(0xffffffffu, uA, off);
            uB += __shfl_xor_sync(0xffffffffu, uB, off);
        }
        if(lane == 0){
            out[ZOUT + (size_t)rA*Sq + s] = uA + bd2r;
            out[ZOUT + (size_t)rB*Sq + s] = uB + bd2r;
        }
    }
}

// ------------------------------------------------------------------
extern "C" void kernel_launch(void* const* d_in, const int* in_sizes, int n_in,
                              void* d_out, int out_size)
{
    const float* X    = (const float*)d_in[0];
    const float* adj  = (const float*)d_in[1];
    const float* se   = (const float*)d_in[2];
    const float* W1   = (const float*)d_in[3];
    const float* b1   = (const float*)d_in[4];
    const float* W2   = (const float*)d_in[5];
    const float* b2   = (const float*)d_in[6];
    const float* W_ih = (const float*)d_in[7];
    const float* W_hh = (const float*)d_in[8];
    const float* b_ih = (const float*)d_in[9];
    const float* b_hh = (const float*)d_in[10];
    const float* D1   = (const float*)d_in[11];
    const float* bd1  = (const float*)d_in[12];
    const float* D2   = (const float*)d_in[13];
    const float* bd2  = (const float*)d_in[14];
    float* out = (float*)d_out;

    const int smem_gates = (68*256 + 256 + 68*72) * 4;                 // 90240
    const int smem_dec   = (64*WPAD + 16*64 + 64*32) * 4;              // 78080
    cudaFuncSetAttribute(k_gates, cudaFuncAttributeMaxDynamicSharedMemorySize, smem_gates);
    cudaFuncSetAttribute(k_dec,   cudaFuncAttributeMaxDynamicSharedMemorySize, smem_dec);

    k_init_h<<<NH/256, 256>>>(se);
    for(int t=0; t<Sq; t++){
        k_cat  <<<(Nq*NCOL)/256, 256>>>(X, t);
        k_sgemm<<<dim3(Nq/256, (NCOL+63)/64), 256>>>(adj);
        k_gates<<<dim3(Nq/64, Bq), 256, smem_gates>>>(W1, b1, W2, b2);
        k_cell <<<(Bq*NH)/256, 256>>>(se);
    }
    k_copy_z<<<(Bq*NH)/256, 256>>>(out);
    k_dec<<<(Bq*Nq)/16, 256, smem_dec>>>(W_ih, W_hh, b_ih, b_hh, D1, bd1, D2, bd2, out);
}

// round 4
// speedup vs baseline: 2.2748x; 2.2748x over previous
#include <cuda_runtime.h>
#include <cuda_bf16.h>
#include <math.h>
#include <stdint.h>

#define Bq 8
#define Sq 12
#define Nq 4096
#define Fq 4
#define Hq 64
#define CHW 68                    // F + H
#define NCOL 544                  // Bq * CHW
#define NPAD 576                  // padded B columns
#define NH  (Nq*Hq)               // 262144
#define N3H (Nq*3*Hq)             // 786432
#define ZOUT ((size_t)Bq*NH)      // offset of recon in output

// -------- persistent scratch (device globals; no allocation) --------
__device__ float g_h[Bq*NH];                        // hidden state [b][n*H+hc]
__device__ float g_a[Nq*NCOL];                      // GEMM out [m][b*68+f]
__device__ float g_gate[Bq*N3H];                    // sigmoid(gc1) torch-flat
__device__ float g_tconv[Bq*NH];                    // tanh(gc2)
__device__ __align__(16) __nv_bfloat16 g_ah[(size_t)Nq*Nq];    // adj hi
__device__ __align__(16) __nv_bfloat16 g_al[(size_t)Nq*Nq];    // adj lo
__device__ __align__(16) __nv_bfloat16 g_bh[(size_t)Nq*NPAD];  // catT hi [k][col]
__device__ __align__(16) __nv_bfloat16 g_bl[(size_t)Nq*NPAD];  // catT lo

__device__ __forceinline__ float sigf(float x){ return 1.f/(1.f+expf(-x)); }

// ---- packed fp32x2 helpers (used by k_gates) ----
__device__ __forceinline__ unsigned long long dup2(float v){
    unsigned long long r;
    asm("mov.b64 %0, {%1, %1};" : "=l"(r) : "f"(v));
    return r;
}
__device__ __forceinline__ void fma2(unsigned long long &d,
                                     unsigned long long a, unsigned long long b){
    asm("fma.rn.f32x2 %0, %1, %2, %0;" : "+l"(d) : "l"(a), "l"(b));
}
__device__ __forceinline__ float2 unpk(unsigned long long v){
    float2 f;
    asm("mov.b64 {%0, %1}, %2;" : "=f"(f.x), "=f"(f.y) : "l"(v));
    return f;
}

// ---- warp MMA helpers (sm_80+ paths, compile for plain compute_103) ----
__device__ __forceinline__ uint32_t smem_u32(const void* p) {
    uint32_t a;
    asm("{ .reg .u64 t; cvta.to.shared.u64 t, %1; cvt.u32.u64 %0, t; }"
        : "=r"(a) : "l"(p));
    return a;
}
__device__ __forceinline__ void cpasync16(uint32_t dst, const void* src){
    asm volatile("cp.async.cg.shared.global [%0], [%1], 16;"
                 :: "r"(dst), "l"(src) : "memory");
}
__device__ __forceinline__ void ldsm4(uint32_t r[4], uint32_t addr){
    asm volatile("ldmatrix.sync.aligned.m8n8.x4.shared.b16 {%0,%1,%2,%3}, [%4];"
                 : "=r"(r[0]), "=r"(r[1]), "=r"(r[2]), "=r"(r[3]) : "r"(addr));
}
__device__ __forceinline__ void ldsm4t(uint32_t r[4], uint32_t addr){
    asm volatile("ldmatrix.sync.aligned.m8n8.x4.trans.shared.b16 {%0,%1,%2,%3}, [%4];"
                 : "=r"(r[0]), "=r"(r[1]), "=r"(r[2]), "=r"(r[3]) : "r"(addr));
}
__device__ __forceinline__ void mma16816(float d[4], const uint32_t a[4],
                                         uint32_t b0, uint32_t b1){
    asm volatile(
        "mma.sync.aligned.m16n8k16.row.col.f32.bf16.bf16.f32 "
        "{%0,%1,%2,%3}, {%4,%5,%6,%7}, {%8,%9}, {%0,%1,%2,%3};"
        : "+f"(d[0]), "+f"(d[1]), "+f"(d[2]), "+f"(d[3])
        : "r"(a[0]), "r"(a[1]), "r"(a[2]), "r"(a[3]), "r"(b0), "r"(b1));
}

// -------- h0 = broadcast struc_emb (+ write catT h-part hi/lo) --------
__global__ void k_init_h(const float* __restrict__ se){
    int j = blockIdx.x*256 + threadIdx.x;     // NH exactly
    int n = j >> 6, hc = j & 63;
    float v = se[j];
    __nv_bfloat16 hi = __float2bfloat16(v);
    __nv_bfloat16 lo = __float2bfloat16(v - __bfloat162float(hi));
    #pragma unroll
    for(int b=0;b<Bq;b++){
        g_h[(size_t)b*NH + j] = v;
        size_t o = (size_t)n*NPAD + b*CHW + 4 + hc;
        g_bh[o] = hi;
        g_bl[o] = lo;
    }
}

// -------- split adj into bf16 hi/lo --------
__global__ void k_split_adj(const float* __restrict__ adj){
    size_t i = (size_t)blockIdx.x*256 + threadIdx.x;   // Nq*Nq exactly
    float v = adj[i];
    __nv_bfloat16 hi = __float2bfloat16(v);
    g_ah[i] = hi;
    g_al[i] = __float2bfloat16(v - __bfloat162float(hi));
}

// -------- catT X-part: cols b*68+f (f<4), per step --------
__global__ void k_catx(const float* __restrict__ X, int t){
    int i = blockIdx.x*256 + threadIdx.x;   // 32*4096 exactly
    int b = i >> 14, f = (i >> 12) & 3, k = i & 4095;
    float v = X[(size_t)((b*Sq + t)*Nq + k)*Fq + f];
    __nv_bfloat16 hi = __float2bfloat16(v);
    size_t o = (size_t)k*NPAD + b*CHW + f;
    g_bh[o] = hi;
    g_bl[o] = __float2bfloat16(v - __bfloat162float(hi));
}

// ===================== HMMA GEMM =====================
// g_a[4096,544] = adj @ cat via bf16 3-term split (hh+hl+lh), fp32 accum.
// BM=128, BN=64, BK=64, 256 threads, warp grid 4x2, warp tile 32x32.
// smem: 2 stages x (A[2][128][64bf16] + B[2][64][64bf16]) = 96KB, XOR swizzle.
#define STAGE_SZ 49152
#define AS_OFF(arr) ((arr)*16384)
#define BS_OFF(arr) (32768 + (arr)*8192)

__device__ __forceinline__ void mma_load_stage(uint32_t dbase, int s, int kt,
                                               int m0, int n0, int tid){
    const uint32_t sb = dbase + (uint32_t)s*STAGE_SZ;
    const int k0 = kt*64;
    // A: 2 arrays x 128 rows x 8 chunks(16B)
    #pragma unroll
    for(int it=0; it<8; it++){
        int i = tid + it*256;
        int arr = i >> 10, rem = i & 1023;
        int row = rem >> 3, c = rem & 7;
        const __nv_bfloat16* src = (arr ? g_al : g_ah)
            + ((size_t)(m0+row) << 12) + k0 + c*8;
        uint32_t dst = sb + AS_OFF(arr) + (uint32_t)row*128 + (uint32_t)((c ^ (row&7))<<4);
        cpasync16(dst, src);
    }
    // B: 2 arrays x 64 k-rows x 8 chunks
    #pragma unroll
    for(int it=0; it<4; it++){
        int i = tid + it*256;
        int arr = i >> 9, rem = i & 511;
        int row = rem >> 3, c = rem & 7;
        const __nv_bfloat16* src = (arr ? g_bl : g_bh)
            + (size_t)(k0+row)*NPAD + n0 + c*8;
        uint32_t dst = sb + BS_OFF(arr) + (uint32_t)row*128 + (uint32_t)((c ^ (row&7))<<4);
        cpasync16(dst, src);
    }
}

__global__ __launch_bounds__(256,1) void k_mma(){
    extern __shared__ char dyn[];
    const uint32_t dbase = smem_u32(dyn);
    const int tid = threadIdx.x;
    const int lane = tid & 31, wid = tid >> 5;
    const int warp_m = wid & 3, warp_n = wid >> 2;
    const int m0 = blockIdx.x * 128;
    const int n0 = blockIdx.y * 64;

    float acc[2][4][4];
    #pragma unroll
    for(int mt=0;mt<2;mt++)
        #pragma unroll
        for(int nt=0;nt<4;nt++)
            #pragma unroll
            for(int q=0;q<4;q++) acc[mt][nt][q] = 0.f;

    mma_load_stage(dbase, 0, 0, m0, n0, tid);
    asm volatile("cp.async.commit_group;" ::: "memory");

    const int lrow = lane & 15, lhalf = lane >> 4;

    for(int kt=0; kt<64; kt++){
        const int s = kt & 1;
        if(kt < 63){
            mma_load_stage(dbase, s^1, kt+1, m0, n0, tid);
            asm volatile("cp.async.commit_group;" ::: "memory");
            asm volatile("cp.async.wait_group 1;" ::: "memory");
        } else {
            asm volatile("cp.async.wait_group 0;" ::: "memory");
        }
        __syncthreads();

        const uint32_t sb = dbase + (uint32_t)s*STAGE_SZ;
        #pragma unroll
        for(int k16=0; k16<4; k16++){
            // A frags (hi & lo), 2 m16 tiles each
            uint32_t ah[2][4], al[2][4];
            #pragma unroll
            for(int mt=0; mt<2; mt++){
                int row = warp_m*32 + mt*16 + lrow;
                int c = k16*2 + lhalf;
                uint32_t off = (uint32_t)row*128 + (uint32_t)((c ^ (row&7))<<4);
                ldsm4(ah[mt], sb + AS_OFF(0) + off);
                ldsm4(al[mt], sb + AS_OFF(1) + off);
            }
            // B frags (hi & lo), 2 n16 tiles each
            uint32_t bh[2][4], bl[2][4];
            #pragma unroll
            for(int nt16=0; nt16<2; nt16++){
                int k = k16*16 + lrow;
                int c = warp_n*4 + nt16*2 + lhalf;
                uint32_t off = (uint32_t)k*128 + (uint32_t)((c ^ (k&7))<<4);
                ldsm4t(bh[nt16], sb + BS_OFF(0) + off);
                ldsm4t(bl[nt16], sb + BS_OFF(1) + off);
            }
            #pragma unroll
            for(int mt=0; mt<2; mt++)
                #pragma unroll
                for(int nt16=0; nt16<2; nt16++)
                    #pragma unroll
                    for(int h8=0; h8<2; h8++){
                        float* d = acc[mt][nt16*2 + h8];
                        uint32_t b0 = bh[nt16][2*h8], b1 = bh[nt16][2*h8+1];
                        mma16816(d, ah[mt], b0, b1);                              // hh
                        mma16816(d, ah[mt], bl[nt16][2*h8], bl[nt16][2*h8+1]);    // hl
                        mma16816(d, al[mt], b0, b1);                              // lh
                    }
        }
        __syncthreads();
    }

    // epilogue: d frag mapping -> rows lane/4 (+8), cols (lane%4)*2
    #pragma unroll
    for(int mt=0; mt<2; mt++){
        #pragma unroll
        for(int nt=0; nt<4; nt++){
            int col = n0 + warp_n*32 + nt*8 + (lane&3)*2;
            if(col < NCOL){
                int r0 = m0 + warp_m*32 + mt*16 + (lane>>2);
                float2 v0; v0.x = acc[mt][nt][0]; v0.y = acc[mt][nt][1];
                float2 v1; v1.x = acc[mt][nt][2]; v1.y = acc[mt][nt][3];
                *(float2*)(g_a + (size_t)r0*NCOL + col)     = v0;
                *(float2*)(g_a + (size_t)(r0+8)*NCOL + col) = v1;
            }
        }
    }
}

// -------- per-node weight GEMM + activations (64 nodes/block, FFMA2) --------
__global__ __launch_bounds__(256,2) void k_gates(
        const float* __restrict__ W1, const float* __restrict__ b1,
        const float* __restrict__ W2, const float* __restrict__ b2){
    extern __shared__ float sm[];
    float* Wc = sm;                 // 68*256
    float* bc = Wc + 68*256;        // 256
    float* at = bc + 256;           // 68*72 (padded, [f][i])
    const int tid = threadIdx.x;
    const int b  = blockIdx.y;
    const int m0 = blockIdx.x * 64;

    for(int idx=tid; idx<68*256; idx+=256){
        int f = idx >> 8, ch = idx & 255;
        Wc[idx] = (ch < 192) ? W1[f*192 + ch] : W2[f*64 + ch - 192];
    }
    bc[tid] = (tid < 192) ? b1[tid] : b2[tid - 192];
    for(int idx=tid; idx<64*68; idx+=256){
        int i = idx / 68, f = idx - i*68;
        at[f*72 + i] = g_a[(size_t)(m0+i)*NCOL + b*CHW + f];
    }
    __syncthreads();

    const int lane = tid & 31, wg = tid >> 5;
    unsigned long long acc[4][8];
    #pragma unroll
    for(int j=0;j<8;j++){
        unsigned long long bias = dup2(bc[lane + 32*j]);
        #pragma unroll
        for(int p=0;p<4;p++) acc[p][j] = bias;
    }

    #pragma unroll 4
    for(int f=0; f<68; f++){
        const ulonglong2 a01 = *(const ulonglong2*)&at[f*72 + wg*8];
        const ulonglong2 a23 = *(const ulonglong2*)&at[f*72 + wg*8 + 4];
        unsigned long long wd[8];
        #pragma unroll
        for(int j=0;j<8;j++) wd[j] = dup2(Wc[f*256 + lane + 32*j]);
        #pragma unroll
        for(int j=0;j<8;j++){
            fma2(acc[0][j], a01.x, wd[j]);
            fma2(acc[1][j], a01.y, wd[j]);
            fma2(acc[2][j], a23.x, wd[j]);
            fma2(acc[3][j], a23.y, wd[j]);
        }
    }

    #pragma unroll
    for(int p=0;p<4;p++){
        const int nlo = m0 + wg*8 + 2*p;
        #pragma unroll
        for(int j=0;j<8;j++){
            const int ch = lane + 32*j;
            float2 u = unpk(acc[p][j]);
            if(ch < 192){
                g_gate[(size_t)b*N3H + (size_t)nlo*192 + ch]       = sigf(u.x);
                g_gate[(size_t)b*N3H + (size_t)(nlo+1)*192 + ch]   = sigf(u.y);
            }else{
                g_tconv[(size_t)b*NH + (size_t)nlo*64 + (ch-192)]     = tanhf(u.x);
                g_tconv[(size_t)b*NH + (size_t)(nlo+1)*64 + (ch-192)] = tanhf(u.y);
            }
        }
    }
}

// -------- LSTM cell elementwise + write catT h-part for next step --------
__global__ void k_cell(const float* __restrict__ se){
    int idx = blockIdx.x*256 + threadIdx.x;     // Bq*NH exactly
    int b = idx >> 18;
    int j = idx & (NH-1);
    const float* gg = g_gate + (size_t)b*N3H;
    float f = gg[j], i = gg[NH + j], o = gg[2*NH + j];
    float c = f*se[j] + i*g_tconv[idx];
    float h = o * tanhf(c);
    g_h[idx] = h;
    int n = j >> 6, hc = j & 63;
    __nv_bfloat16 hi = __float2bfloat16(h);
    size_t ofs = (size_t)n*NPAD + b*CHW + 4 + hc;
    g_bh[ofs] = hi;
    g_bl[ofs] = __float2bfloat16(h - __bfloat162float(hi));
}

// -------- copy z to output --------
__global__ void k_copy_z(float* __restrict__ out){
    int idx = blockIdx.x*256 + threadIdx.x;     // Bq*NH exactly
    out[idx] = g_h[idx];
}

// -------- fused decoder: x_gates + 12-step LSTM + MLP head --------
#define WPAD 257
__global__ __launch_bounds__(256,2) void k_dec(
    const float* __restrict__ W_ih, const float* __restrict__ W_hh,
    const float* __restrict__ b_ih, const float* __restrict__ b_hh,
    const float* __restrict__ D1,   const float* __restrict__ bd1,
    const float* __restrict__ D2,   const float* __restrict__ bd2,
    float* __restrict__ out)
{
    extern __shared__ float sm[];
    float* Wsh = sm;                 // [64][257]
    float* hsh = Wsh + 64*WPAD;      // [16][64]
    float* D1s = hsh + 16*64;        // [64][32]
    const int tid = threadIdx.x, lane = tid & 31, w = tid >> 5;
    const int rA = blockIdx.x*16 + w*2;
    const int rB = rA + 1;

    for(int idx=tid; idx<256*64; idx+=256){
        int gc = idx >> 6, k = idx & 63;
        Wsh[k*WPAD + gc] = W_ih[idx];
    }
    for(int idx=tid; idx<64*32; idx+=256) D1s[idx] = D1[idx];

    float* hA = hsh + (w*2)*64;
    float* hB = hA + 64;
    hA[lane]    = g_h[(size_t)rA*64 + lane];
    hA[lane+32] = g_h[(size_t)rA*64 + lane + 32];
    hB[lane]    = g_h[(size_t)rB*64 + lane];
    hB[lane+32] = g_h[(size_t)rB*64 + lane + 32];
    __syncthreads();

    float xgA[8], xgB[8];
    #pragma unroll
    for(int i=0;i<8;i++){
        int gc = lane + 32*i;
        float bb = b_ih[gc] + b_hh[gc];
        xgA[i] = bb; xgB[i] = bb;
    }
    for(int k=0;k<64;k++){
        float ha = hA[k], hb = hB[k];
        #pragma unroll
        for(int i=0;i<8;i++){
            float wv = Wsh[k*WPAD + lane + 32*i];
            xgA[i] += ha*wv; xgB[i] += hb*wv;
        }
    }
    __syncthreads();
    for(int idx=tid; idx<256*64; idx+=256){
        int gc = idx >> 6, k = idx & 63;
        Wsh[k*WPAD + gc] = W_hh[idx];
    }
    hA[lane]=0.f; hA[lane+32]=0.f; hB[lane]=0.f; hB[lane+32]=0.f;
    float cA0=0.f, cA1=0.f, cB0=0.f, cB1=0.f;
    const float bd1r = bd1[lane];
    const float d2r  = D2[lane];
    const float bd2r = bd2[0];
    __syncthreads();

    for(int s=0; s<Sq; s++){
        float aA[8], aB[8];
        #pragma unroll
        for(int i=0;i<8;i++){ aA[i]=xgA[i]; aB[i]=xgB[i]; }
        for(int k=0;k<64;k++){
            float ha = hA[k], hb = hB[k];
            #pragma unroll
            for(int i=0;i<8;i++){
                float wv = Wsh[k*WPAD + lane + 32*i];
                aA[i] += ha*wv; aB[i] += hb*wv;
            }
        }
        float hA0,hA1,hB0,hB1;
        {
            float ig=sigf(aA[0]), fg=sigf(aA[2]), gg=tanhf(aA[4]), og=sigf(aA[6]);
            cA0 = fg*cA0 + ig*gg; hA0 = og*tanhf(cA0);
            ig=sigf(aA[1]); fg=sigf(aA[3]); gg=tanhf(aA[5]); og=sigf(aA[7]);
            cA1 = fg*cA1 + ig*gg; hA1 = og*tanhf(cA1);
            ig=sigf(aB[0]); fg=sigf(aB[2]); gg=tanhf(aB[4]); og=sigf(aB[6]);
            cB0 = fg*cB0 + ig*gg; hB0 = og*tanhf(cB0);
            ig=sigf(aB[1]); fg=sigf(aB[3]); gg=tanhf(aB[5]); og=sigf(aB[7]);
            cB1 = fg*cB1 + ig*gg; hB1 = og*tanhf(cB1);
        }
        __syncwarp();
        hA[lane]=hA0; hA[lane+32]=hA1; hB[lane]=hB0; hB[lane+32]=hB1;
        __syncwarp();

        float uA = bd1r, uB = bd1r;
        for(int k=0;k<64;k++){
            float dv = D1s[k*32 + lane];
            uA += hA[k]*dv; uB += hB[k]*dv;
        }
        uA = fmaxf(uA, 0.f)*d2r;
        uB = fmaxf(uB, 0.f)*d2r;
        #pragma unroll
        for(int off=16; off; off>>=1){
            uA += __shfl_xor_sync(0xffffffffu, uA, off);
            uB += __shfl_xor_sync(0xffffffffu, uB, off);
        }
        if(lane == 0){
            out[ZOUT + (size_t)rA*Sq + s] = uA + bd2r;
            out[ZOUT + (size_t)rB*Sq + s] = uB + bd2r;
        }
    }
}

// ------------------------------------------------------------------
extern "C" void kernel_launch(void* const* d_in, const int* in_sizes, int n_in,
                              void* d_out, int out_size)
{
    const float* X    = (const float*)d_in[0];
    const float* adj  = (const float*)d_in[1];
    const float* se   = (const float*)d_in[2];
    const float* W1   = (const float*)d_in[3];
    const float* b1   = (const float*)d_in[4];
    const float* W2   = (const float*)d_in[5];
    const float* b2   = (const float*)d_in[6];
    const float* W_ih = (const float*)d_in[7];
    const float* W_hh = (const float*)d_in[8];
    const float* b_ih = (const float*)d_in[9];
    const float* b_hh = (const float*)d_in[10];
    const float* D1   = (const float*)d_in[11];
    const float* bd1  = (const float*)d_in[12];
    const float* D2   = (const float*)d_in[13];
    const float* bd2  = (const float*)d_in[14];
    float* out = (float*)d_out;

    const int smem_gates = (68*256 + 256 + 68*72) * 4;                 // 90240
    const int smem_dec   = (64*WPAD + 16*64 + 64*32) * 4;              // 78080
    const int smem_mma   = 2*STAGE_SZ;                                 // 98304
    cudaFuncSetAttribute(k_gates, cudaFuncAttributeMaxDynamicSharedMemorySize, smem_gates);
    cudaFuncSetAttribute(k_dec,   cudaFuncAttributeMaxDynamicSharedMemorySize, smem_dec);
    cudaFuncSetAttribute(k_mma,   cudaFuncAttributeMaxDynamicSharedMemorySize, smem_mma);

    k_split_adj<<<(int)((Nq*(size_t)Nq)/256), 256>>>(adj);
    k_init_h<<<NH/256, 256>>>(se);
    for(int t=0; t<Sq; t++){
        k_catx<<<(32*4096)/256, 256>>>(X, t);
        k_mma <<<dim3(Nq/128, 9), 256, smem_mma>>>();
        k_gates<<<dim3(Nq/64, Bq), 256, smem_gates>>>(W1, b1, W2, b2);
        k_cell <<<(Bq*NH)/256, 256>>>(se);
    }
    k_copy_z<<<(Bq*NH)/256, 256>>>(out);
    k_dec<<<(Bq*Nq)/16, 256, smem_dec>>>(W_ih, W_hh, b_ih, b_hh, D1, bd1, D2, bd2, out);
}

// round 5
// speedup vs baseline: 2.4250x; 1.0660x over previous
#include <cuda_runtime.h>
#include <cuda_bf16.h>
#include <math.h>
#include <stdint.h>

#define Bq 8
#define Sq 12
#define Nq 4096
#define Fq 4
#define Hq 64
#define CHW 68                    // F + H
#define NCOL 544                  // Bq * CHW
#define NPAD 576                  // padded B columns
#define NH  (Nq*Hq)               // 262144
#define N3H (Nq*3*Hq)             // 786432
#define ZOUT ((size_t)Bq*NH)      // offset of recon in output

// -------- persistent scratch (device globals; no allocation) --------
__device__ float g_h[Bq*NH];                        // hidden state [b][n*H+hc]
__device__ float g_a[Nq*NCOL];                      // GEMM out [m][b*68+f]
__device__ float g_gate[Bq*N3H];                    // sigmoid(gc1) torch-flat
__device__ float g_tconv[Bq*NH];                    // tanh(gc2)
__device__ __align__(16) __nv_bfloat16 g_ah[(size_t)Nq*Nq];    // adj hi
__device__ __align__(16) __nv_bfloat16 g_al[(size_t)Nq*Nq];    // adj lo
__device__ __align__(16) __nv_bfloat16 g_bh[(size_t)Nq*NPAD];  // catT hi [k][col]
__device__ __align__(16) __nv_bfloat16 g_bl[(size_t)Nq*NPAD];  // catT lo
__device__ __align__(16) __nv_bfloat16 g_wh[80*256];           // W1|W2 hi [k][ch]
__device__ __align__(16) __nv_bfloat16 g_wl[80*256];           // W1|W2 lo

__device__ __forceinline__ float sigf(float x){ return 1.f/(1.f+expf(-x)); }

// ---- warp MMA helpers ----
__device__ __forceinline__ uint32_t smem_u32(const void* p) {
    uint32_t a;
    asm("{ .reg .u64 t; cvta.to.shared.u64 t, %1; cvt.u32.u64 %0, t; }"
        : "=r"(a) : "l"(p));
    return a;
}
__device__ __forceinline__ void cpasync16(uint32_t dst, const void* src){
    asm volatile("cp.async.cg.shared.global [%0], [%1], 16;"
                 :: "r"(dst), "l"(src) : "memory");
}
__device__ __forceinline__ void ldsm4(uint32_t r[4], uint32_t addr){
    asm volatile("ldmatrix.sync.aligned.m8n8.x4.shared.b16 {%0,%1,%2,%3}, [%4];"
                 : "=r"(r[0]), "=r"(r[1]), "=r"(r[2]), "=r"(r[3]) : "r"(addr));
}
__device__ __forceinline__ void ldsm4t(uint32_t r[4], uint32_t addr){
    asm volatile("ldmatrix.sync.aligned.m8n8.x4.trans.shared.b16 {%0,%1,%2,%3}, [%4];"
                 : "=r"(r[0]), "=r"(r[1]), "=r"(r[2]), "=r"(r[3]) : "r"(addr));
}
__device__ __forceinline__ void mma16816(float d[4], const uint32_t a[4],
                                         uint32_t b0, uint32_t b1){
    asm volatile(
        "mma.sync.aligned.m16n8k16.row.col.f32.bf16.bf16.f32 "
        "{%0,%1,%2,%3}, {%4,%5,%6,%7}, {%8,%9}, {%0,%1,%2,%3};"
        : "+f"(d[0]), "+f"(d[1]), "+f"(d[2]), "+f"(d[3])
        : "r"(a[0]), "r"(a[1]), "r"(a[2]), "r"(a[3]), "r"(b0), "r"(b1));
}

// -------- h0 = broadcast struc_emb (+ write catT h-part hi/lo) --------
__global__ void k_init_h(const float* __restrict__ se){
    int j = blockIdx.x*256 + threadIdx.x;     // NH exactly
    int n = j >> 6, hc = j & 63;
    float v = se[j];
    __nv_bfloat16 hi = __float2bfloat16(v);
    __nv_bfloat16 lo = __float2bfloat16(v - __bfloat162float(hi));
    #pragma unroll
    for(int b=0;b<Bq;b++){
        g_h[(size_t)b*NH + j] = v;
        size_t o = (size_t)n*NPAD + b*CHW + 4 + hc;
        g_bh[o] = hi;
        g_bl[o] = lo;
    }
}

// -------- split adj into bf16 hi/lo --------
__global__ void k_split_adj(const float* __restrict__ adj){
    size_t i = (size_t)blockIdx.x*256 + threadIdx.x;   // Nq*Nq exactly
    float v = adj[i];
    __nv_bfloat16 hi = __float2bfloat16(v);
    g_ah[i] = hi;
    g_al[i] = __float2bfloat16(v - __bfloat162float(hi));
}

// -------- split W1|W2 into bf16 hi/lo [80][256], rows>=68 zero --------
__global__ void k_split_w(const float* __restrict__ W1, const float* __restrict__ W2){
    int idx = blockIdx.x*256 + threadIdx.x;   // 80*256 exactly
    int f = idx >> 8, ch = idx & 255;
    float v = 0.f;
    if(f < 68) v = (ch < 192) ? W1[f*192 + ch] : W2[f*64 + ch - 192];
    __nv_bfloat16 hi = __float2bfloat16(v);
    g_wh[idx] = hi;
    g_wl[idx] = __float2bfloat16(v - __bfloat162float(hi));
}

// -------- catT X-part: cols b*68+f (f<4), per step --------
__global__ void k_catx(const float* __restrict__ X, int t){
    int i = blockIdx.x*256 + threadIdx.x;   // 32*4096 exactly
    int b = i >> 14, f = (i >> 12) & 3, k = i & 4095;
    float v = X[(size_t)((b*Sq + t)*Nq + k)*Fq + f];
    __nv_bfloat16 hi = __float2bfloat16(v);
    size_t o = (size_t)k*NPAD + b*CHW + f;
    g_bh[o] = hi;
    g_bl[o] = __float2bfloat16(v - __bfloat162float(hi));
}

// ===================== HMMA GEMM (encoder diffusion) =====================
// g_a[4096,544] = adj @ cat via bf16 3-term split, fp32 accum.
// BM=128, BN=64, BK=32, 3-stage cp.async, 2 CTAs/SM, 256 thr, warp 4x2.
#define MSTAGE 24576
#define MA_HI  0
#define MA_LO  8192
#define MB_HI  16384
#define MB_LO  20480

__device__ __forceinline__ void mma_load_stage(uint32_t dbase, int s, int kt,
                                               int m0, int n0, int tid){
    const uint32_t sb = dbase + (uint32_t)s*MSTAGE;
    const int k0 = kt*32;
    // A: 2 arrays x 128 rows x 4 chunks(16B)
    #pragma unroll
    for(int it=0; it<4; it++){
        int i = tid + it*256;
        int arr = i >> 9, rem = i & 511;
        int row = rem >> 2, c = rem & 3;
        const __nv_bfloat16* src = (arr ? g_al : g_ah)
            + ((size_t)(m0+row) << 12) + k0 + c*8;
        uint32_t dst = sb + (arr ? MA_LO : MA_HI)
            + (uint32_t)row*64 + (uint32_t)((c ^ ((row>>1)&3))<<4);
        cpasync16(dst, src);
    }
    // B: 2 arrays x 32 k-rows x 8 chunks
    #pragma unroll
    for(int it=0; it<2; it++){
        int i = tid + it*256;
        int arr = i >> 8, rem = i & 255;
        int row = rem >> 3, c = rem & 7;
        const __nv_bfloat16* src = (arr ? g_bl : g_bh)
            + (size_t)(k0+row)*NPAD + n0 + c*8;
        uint32_t dst = sb + (arr ? MB_LO : MB_HI)
            + (uint32_t)row*128 + (uint32_t)((c ^ (row&7))<<4);
        cpasync16(dst, src);
    }
}

__global__ __launch_bounds__(256,2) void k_mma(){
    extern __shared__ char dyn[];
    const uint32_t dbase = smem_u32(dyn);
    const int tid = threadIdx.x;
    const int lane = tid & 31, wid = tid >> 5;
    const int warp_m = wid & 3, warp_n = wid >> 2;
    const int m0 = blockIdx.x * 128;
    const int n0 = blockIdx.y * 64;
    const int lrow = lane & 15, lhalf = lane >> 4;

    float acc[2][4][4];
    #pragma unroll
    for(int mt=0;mt<2;mt++)
        #pragma unroll
        for(int nt=0;nt<4;nt++)
            #pragma unroll
            for(int q=0;q<4;q++) acc[mt][nt][q] = 0.f;

    mma_load_stage(dbase, 0, 0, m0, n0, tid);
    asm volatile("cp.async.commit_group;" ::: "memory");
    mma_load_stage(dbase, 1, 1, m0, n0, tid);
    asm volatile("cp.async.commit_group;" ::: "memory");

    int s_cur = 0;
    for(int kt=0; kt<128; kt++){
        if(kt < 127){ asm volatile("cp.async.wait_group 1;" ::: "memory"); }
        else        { asm volatile("cp.async.wait_group 0;" ::: "memory"); }
        __syncthreads();

        if(kt + 2 < 128){
            int s2 = s_cur + 2; if(s2 >= 3) s2 -= 3;
            mma_load_stage(dbase, s2, kt+2, m0, n0, tid);
            asm volatile("cp.async.commit_group;" ::: "memory");
        }

        const uint32_t sb = dbase + (uint32_t)s_cur*MSTAGE;
        #pragma unroll
        for(int k16=0; k16<2; k16++){
            uint32_t ah[2][4], al[2][4];
            #pragma unroll
            for(int mt=0; mt<2; mt++){
                int row = warp_m*32 + mt*16 + lrow;
                int c = k16*2 + lhalf;
                uint32_t off = (uint32_t)row*64 + (uint32_t)((c ^ ((row>>1)&3))<<4);
                ldsm4(ah[mt], sb + MA_HI + off);
                ldsm4(al[mt], sb + MA_LO + off);
            }
            uint32_t bh[2][4], bl[2][4];
            #pragma unroll
            for(int nt16=0; nt16<2; nt16++){
                int k = k16*16 + lrow;
                int c = warp_n*4 + nt16*2 + lhalf;
                uint32_t off = (uint32_t)k*128 + (uint32_t)((c ^ (k&7))<<4);
                ldsm4t(bh[nt16], sb + MB_HI + off);
                ldsm4t(bl[nt16], sb + MB_LO + off);
            }
            #pragma unroll
            for(int mt=0; mt<2; mt++)
                #pragma unroll
                for(int nt16=0; nt16<2; nt16++)
                    #pragma unroll
                    for(int h8=0; h8<2; h8++){
                        float* d = acc[mt][nt16*2 + h8];
                        uint32_t b0 = bh[nt16][2*h8], b1 = bh[nt16][2*h8+1];
                        mma16816(d, ah[mt], b0, b1);
                        mma16816(d, ah[mt], bl[nt16][2*h8], bl[nt16][2*h8+1]);
                        mma16816(d, al[mt], b0, b1);
                    }
        }
        s_cur++; if(s_cur == 3) s_cur = 0;
    }

    #pragma unroll
    for(int mt=0; mt<2; mt++){
        #pragma unroll
        for(int nt=0; nt<4; nt++){
            int col = n0 + warp_n*32 + nt*8 + (lane&3)*2;
            if(col < NCOL){
                int r0 = m0 + warp_m*32 + mt*16 + (lane>>2);
                float2 v0; v0.x = acc[mt][nt][0]; v0.y = acc[mt][nt][1];
                float2 v1; v1.x = acc[mt][nt][2]; v1.y = acc[mt][nt][3];
                *(float2*)(g_a + (size_t)r0*NCOL + col)     = v0;
                *(float2*)(g_a + (size_t)(r0+8)*NCOL + col) = v1;
            }
        }
    }
}

// ===================== HMMA gates GEMM + activations =====================
// Per block: 128 nodes x 128 channels x batch b. K=80 (68 + zero pad).
// a split to bf16 hi/lo in smem (stride 88), W pre-split (stride 136).
#define GA_ST 88
#define GW_ST 136
#define GSM_AH 0
#define GSM_AL (128*GA_ST*2)
#define GSM_WH (2*128*GA_ST*2)
#define GSM_WL (2*128*GA_ST*2 + 80*GW_ST*2)
#define GSM_BC (2*128*GA_ST*2 + 2*80*GW_ST*2)
#define GSM_TOT (GSM_BC + 128*4)

__global__ __launch_bounds__(256,1) void k_gates_mma(
        const float* __restrict__ b1, const float* __restrict__ b2){
    extern __shared__ char smg[];
    const uint32_t sb = smem_u32(smg);
    __nv_bfloat16* aH = (__nv_bfloat16*)(smg + GSM_AH);
    __nv_bfloat16* aL = (__nv_bfloat16*)(smg + GSM_AL);
    __nv_bfloat16* wH = (__nv_bfloat16*)(smg + GSM_WH);
    __nv_bfloat16* wL = (__nv_bfloat16*)(smg + GSM_WL);
    float* bc = (float*)(smg + GSM_BC);
    const int tid = threadIdx.x, lane = tid & 31, wid = tid >> 5;
    const int warp_m = wid & 3, warp_n = wid >> 2;
    const int m0 = blockIdx.x * 128;
    const int b  = blockIdx.y;
    const int z  = blockIdx.z;                // channel half: ch = z*128 + col
    const int lrow = lane & 15, lhalf = lane >> 4;

    // fill a-tile (hi/lo), zero pad cols 68..87
    for(int idx=tid; idx<128*GA_ST; idx+=256){
        int i = idx / GA_ST, f = idx - i*GA_ST;
        float v = (f < CHW) ? g_a[(size_t)(m0+i)*NCOL + b*CHW + f] : 0.f;
        __nv_bfloat16 hi = __float2bfloat16(v);
        aH[idx] = hi;
        aL[idx] = __float2bfloat16(v - __bfloat162float(hi));
    }
    // fill W tiles (pre-split), cols z*128..z*128+127; pad cols zero
    for(int idx=tid; idx<80*GW_ST; idx+=256){
        int f = idx / GW_ST, c = idx - f*GW_ST;
        __nv_bfloat16 zero = __float2bfloat16(0.f);
        wH[idx] = (c < 128) ? g_wh[f*256 + z*128 + c] : zero;
        wL[idx] = (c < 128) ? g_wl[f*256 + z*128 + c] : zero;
    }
    if(tid < 128){
        int ch = z*128 + tid;
        bc[tid] = (ch < 192) ? b1[ch] : b2[ch - 192];
    }
    __syncthreads();

    float acc[2][8][4];
    #pragma unroll
    for(int mt=0;mt<2;mt++)
        #pragma unroll
        for(int nt=0;nt<8;nt++)
            #pragma unroll
            for(int q=0;q<4;q++) acc[mt][nt][q] = 0.f;

    #pragma unroll
    for(int k16=0; k16<5; k16++){
        uint32_t ah[2][4], al[2][4];
        #pragma unroll
        for(int mt=0; mt<2; mt++){
            int row = warp_m*32 + mt*16 + lrow;
            uint32_t off = (uint32_t)row*(GA_ST*2) + (uint32_t)(k16*32 + lhalf*16);
            ldsm4(ah[mt], sb + GSM_AH + off);
            ldsm4(al[mt], sb + GSM_AL + off);
        }
        uint32_t bh[4][4], bl[4][4];
        #pragma unroll
        for(int nt16=0; nt16<4; nt16++){
            int k = k16*16 + lrow;
            uint32_t off = (uint32_t)k*(GW_ST*2)
                + (uint32_t)(warp_n*128 + nt16*32 + lhalf*16);
            ldsm4t(bh[nt16], sb + GSM_WH + off);
            ldsm4t(bl[nt16], sb + GSM_WL + off);
        }
        #pragma unroll
        for(int mt=0; mt<2; mt++)
            #pragma unroll
            for(int nt16=0; nt16<4; nt16++)
                #pragma unroll
                for(int h8=0; h8<2; h8++){
                    float* d = acc[mt][nt16*2 + h8];
                    uint32_t b0 = bh[nt16][2*h8], b1v = bh[nt16][2*h8+1];
                    mma16816(d, ah[mt], b0, b1v);
                    mma16816(d, ah[mt], bl[nt16][2*h8], bl[nt16][2*h8+1]);
                    mma16816(d, al[mt], b0, b1v);
                }
    }

    // epilogue: bias + activation + scatter
    #pragma unroll
    for(int mt=0; mt<2; mt++){
        #pragma unroll
        for(int nt=0; nt<8; nt++){
            int col = warp_n*64 + nt*8 + (lane&3)*2;
            int ch  = z*128 + col;
            float bb0 = bc[col], bb1 = bc[col+1];
            int r0 = m0 + warp_m*32 + mt*16 + (lane>>2);
            #pragma unroll
            for(int hf=0; hf<2; hf++){
                int node = r0 + 8*hf;
                float v0 = acc[mt][nt][2*hf]   + bb0;
                float v1 = acc[mt][nt][2*hf+1] + bb1;
                if(ch < 192){
                    float2 o; o.x = sigf(v0); o.y = sigf(v1);
                    *(float2*)(g_gate + (size_t)b*N3H + (size_t)node*192 + ch) = o;
                }else{
                    float2 o; o.x = tanhf(v0); o.y = tanhf(v1);
                    *(float2*)(g_tconv + (size_t)b*NH + (size_t)node*64 + (ch-192)) = o;
                }
            }
        }
    }
}

// -------- LSTM cell elementwise + write catT h-part for next step --------
__global__ void k_cell(const float* __restrict__ se){
    int idx = blockIdx.x*256 + threadIdx.x;     // Bq*NH exactly
    int b = idx >> 18;
    int j = idx & (NH-1);
    const float* gg = g_gate + (size_t)b*N3H;
    float f = gg[j], i = gg[NH + j], o = gg[2*NH + j];
    float c = f*se[j] + i*g_tconv[idx];
    float h = o * tanhf(c);
    g_h[idx] = h;
    int n = j >> 6, hc = j & 63;
    __nv_bfloat16 hi = __float2bfloat16(h);
    size_t ofs = (size_t)n*NPAD + b*CHW + 4 + hc;
    g_bh[ofs] = hi;
    g_bl[ofs] = __float2bfloat16(h - __bfloat162float(hi));
}

// -------- copy z to output --------
__global__ void k_copy_z(float* __restrict__ out){
    int idx = blockIdx.x*256 + threadIdx.x;     // Bq*NH exactly
    out[idx] = g_h[idx];
}

// -------- fused decoder: x_gates + 12-step LSTM + MLP head --------
#define WPAD 257
__global__ __launch_bounds__(256,2) void k_dec(
    const float* __restrict__ W_ih, const float* __restrict__ W_hh,
    const float* __restrict__ b_ih, const float* __restrict__ b_hh,
    const float* __restrict__ D1,   const float* __restrict__ bd1,
    const float* __restrict__ D2,   const float* __restrict__ bd2,
    float* __restrict__ out)
{
    extern __shared__ float sm[];
    float* Wsh = sm;                 // [64][257]
    float* hsh = Wsh + 64*WPAD;      // [16][64]
    float* D1s = hsh + 16*64;        // [64][32]
    const int tid = threadIdx.x, lane = tid & 31, w = tid >> 5;
    const int rA = blockIdx.x*16 + w*2;
    const int rB = rA + 1;

    for(int idx=tid; idx<256*64; idx+=256){
        int gc = idx >> 6, k = idx & 63;
        Wsh[k*WPAD + gc] = W_ih[idx];
    }
    for(int idx=tid; idx<64*32; idx+=256) D1s[idx] = D1[idx];

    float* hA = hsh + (w*2)*64;
    float* hB = hA + 64;
    hA[lane]    = g_h[(size_t)rA*64 + lane];
    hA[lane+32] = g_h[(size_t)rA*64 + lane + 32];
    hB[lane]    = g_h[(size_t)rB*64 + lane];
    hB[lane+32] = g_h[(size_t)rB*64 + lane + 32];
    __syncthreads();

    float xgA[8], xgB[8];
    #pragma unroll
    for(int i=0;i<8;i++){
        int gc = lane + 32*i;
        float bb = b_ih[gc] + b_hh[gc];
        xgA[i] = bb; xgB[i] = bb;
    }
    for(int k=0;k<64;k++){
        float ha = hA[k], hb = hB[k];
        #pragma unroll
        for(int i=0;i<8;i++){
            float wv = Wsh[k*WPAD + lane + 32*i];
            xgA[i] += ha*wv; xgB[i] += hb*wv;
        }
    }
    __syncthreads();
    for(int idx=tid; idx<256*64; idx+=256){
        int gc = idx >> 6, k = idx & 63;
        Wsh[k*WPAD + gc] = W_hh[idx];
    }
    hA[lane]=0.f; hA[lane+32]=0.f; hB[lane]=0.f; hB[lane+32]=0.f;
    float cA0=0.f, cA1=0.f, cB0=0.f, cB1=0.f;
    const float bd1r = bd1[lane];
    const float d2r  = D2[lane];
    const float bd2r = bd2[0];
    __syncthreads();

    for(int s=0; s<Sq; s++){
        float aA[8], aB[8];
        #pragma unroll
        for(int i=0;i<8;i++){ aA[i]=xgA[i]; aB[i]=xgB[i]; }
        for(int k=0;k<64;k++){
            float ha = hA[k], hb = hB[k];
            #pragma unroll
            for(int i=0;i<8;i++){
                float wv = Wsh[k*WPAD + lane + 32*i];
                aA[i] += ha*wv; aB[i] += hb*wv;
            }
        }
        float hA0,hA1,hB0,hB1;
        {
            float ig=sigf(aA[0]), fg=sigf(aA[2]), gg=tanhf(aA[4]), og=sigf(aA[6]);
            cA0 = fg*cA0 + ig*gg; hA0 = og*tanhf(cA0);
            ig=sigf(aA[1]); fg=sigf(aA[3]); gg=tanhf(aA[5]); og=sigf(aA[7]);
            cA1 = fg*cA1 + ig*gg; hA1 = og*tanhf(cA1);
            ig=sigf(aB[0]); fg=sigf(aB[2]); gg=tanhf(aB[4]); og=sigf(aB[6]);
            cB0 = fg*cB0 + ig*gg; hB0 = og*tanhf(cB0);
            ig=sigf(aB[1]); fg=sigf(aB[3]); gg=tanhf(aB[5]); og=sigf(aB[7]);
            cB1 = fg*cB1 + ig*gg; hB1 = og*tanhf(cB1);
        }
        __syncwarp();
        hA[lane]=hA0; hA[lane+32]=hA1; hB[lane]=hB0; hB[lane+32]=hB1;
        __syncwarp();

        float uA = bd1r, uB = bd1r;
        for(int k=0;k<64;k++){
            float dv = D1s[k*32 + lane];
            uA += hA[k]*dv; uB += hB[k]*dv;
        }
        uA = fmaxf(uA, 0.f)*d2r;
        uB = fmaxf(uB, 0.f)*d2r;
        #pragma unroll
        for(int off=16; off; off>>=1){
            uA += __shfl_xor_sync(0xffffffffu, uA, off);
            uB += __shfl_xor_sync(0xffffffffu, uB, off);
        }
        if(lane == 0){
            out[ZOUT + (size_t)rA*Sq + s] = uA + bd2r;
            out[ZOUT + (size_t)rB*Sq + s] = uB + bd2r;
        }
    }
}

// ------------------------------------------------------------------
extern "C" void kernel_launch(void* const* d_in, const int* in_sizes, int n_in,
                              void* d_out, int out_size)
{
    const float* X    = (const float*)d_in[0];
    const float* adj  = (const float*)d_in[1];
    const float* se   = (const float*)d_in[2];
    const float* W1   = (const float*)d_in[3];
    const float* b1   = (const float*)d_in[4];
    const float* W2   = (const float*)d_in[5];
    const float* b2   = (const float*)d_in[6];
    const float* W_ih = (const float*)d_in[7];
    const float* W_hh = (const float*)d_in[8];
    const float* b_ih = (const float*)d_in[9];
    const float* b_hh = (const float*)d_in[10];
    const float* D1   = (const float*)d_in[11];
    const float* bd1  = (const float*)d_in[12];
    const float* D2   = (const float*)d_in[13];
    const float* bd2  = (const float*)d_in[14];
    float* out = (float*)d_out;

    const int smem_dec   = (64*WPAD + 16*64 + 64*32) * 4;              // 78080
    const int smem_mma   = 3*MSTAGE;                                   // 73728
    cudaFuncSetAttribute(k_dec,       cudaFuncAttributeMaxDynamicSharedMemorySize, smem_dec);
    cudaFuncSetAttribute(k_mma,       cudaFuncAttributeMaxDynamicSharedMemorySize, smem_mma);
    cudaFuncSetAttribute(k_gates_mma, cudaFuncAttributeMaxDynamicSharedMemorySize, GSM_TOT);

    k_split_adj<<<(int)((Nq*(size_t)Nq)/256), 256>>>(adj);
    k_split_w<<<80, 256>>>(W1, W2);
    k_init_h<<<NH/256, 256>>>(se);
    for(int t=0; t<Sq; t++){
        k_catx<<<(32*4096)/256, 256>>>(X, t);
        k_mma <<<dim3(Nq/128, 9), 256, smem_mma>>>();
        k_gates_mma<<<dim3(Nq/128, Bq, 2), 256, GSM_TOT>>>(b1, b2);
        k_cell <<<(Bq*NH)/256, 256>>>(se);
    }
    k_copy_z<<<(Bq*NH)/256, 256>>>(out);
    k_dec<<<(Bq*Nq)/16, 256, smem_dec>>>(W_ih, W_hh, b_ih, b_hh, D1, bd1, D2, bd2, out);
}

// round 6
// speedup vs baseline: 2.5839x; 1.0655x over previous
#include <cuda_runtime.h>
#include <cuda_bf16.h>
#include <math.h>
#include <stdint.h>

#define Bq 8
#define Sq 12
#define Nq 4096
#define Fq 4
#define Hq 64
#define CHW 68                    // F + H
#define NCOL 544                  // Bq * CHW
#define NPAD 576                  // padded B columns
#define NH  (Nq*Hq)               // 262144
#define N3H (Nq*3*Hq)             // 786432
#define ZOUT ((size_t)Bq*NH)      // offset of recon in output

// -------- persistent scratch (device globals; no allocation) --------
__device__ float g_h[Bq*NH];                        // hidden state [b][n*H+hc]
__device__ float g_a[Nq*NCOL];                      // GEMM out [m][b*68+f]
__device__ float g_gate[Bq*N3H];                    // sigmoid(gc1) torch-flat
__device__ float g_tconv[Bq*NH];                    // tanh(gc2)
__device__ __align__(16) __nv_bfloat16 g_ah[(size_t)Nq*Nq];    // adj hi
__device__ __align__(16) __nv_bfloat16 g_al[(size_t)Nq*Nq];    // adj lo
__device__ __align__(16) __nv_bfloat16 g_bh[(size_t)Nq*NPAD];  // catT hi [k][col]
__device__ __align__(16) __nv_bfloat16 g_bl[(size_t)Nq*NPAD];  // catT lo
__device__ __align__(16) __nv_bfloat16 g_wh[80*256];           // W1|W2 hi [k][ch]
__device__ __align__(16) __nv_bfloat16 g_wl[80*256];           // W1|W2 lo
// decoder pre-split weights (column-permuted: col = hc*4 + gate)
__device__ __align__(16) __nv_bfloat16 g_dwih_h[64*256];
__device__ __align__(16) __nv_bfloat16 g_dwih_l[64*256];
__device__ __align__(16) __nv_bfloat16 g_dwhh_h[64*256];
__device__ __align__(16) __nv_bfloat16 g_dwhh_l[64*256];
__device__ __align__(16) __nv_bfloat16 g_d1h[64*32];
__device__ __align__(16) __nv_bfloat16 g_d1l[64*32];
__device__ float g_dbb[256];                        // permuted b_ih+b_hh

__device__ __forceinline__ float sigf(float x){ return 1.f/(1.f+expf(-x)); }

// ---- warp MMA helpers ----
__device__ __forceinline__ uint32_t smem_u32(const void* p) {
    uint32_t a;
    asm("{ .reg .u64 t; cvta.to.shared.u64 t, %1; cvt.u32.u64 %0, t; }"
        : "=r"(a) : "l"(p));
    return a;
}
__device__ __forceinline__ void cpasync16(uint32_t dst, const void* src){
    asm volatile("cp.async.cg.shared.global [%0], [%1], 16;"
                 :: "r"(dst), "l"(src) : "memory");
}
__device__ __forceinline__ void ldsm4(uint32_t r[4], uint32_t addr){
    asm volatile("ldmatrix.sync.aligned.m8n8.x4.shared.b16 {%0,%1,%2,%3}, [%4];"
                 : "=r"(r[0]), "=r"(r[1]), "=r"(r[2]), "=r"(r[3]) : "r"(addr));
}
__device__ __forceinline__ void ldsm4t(uint32_t r[4], uint32_t addr){
    asm volatile("ldmatrix.sync.aligned.m8n8.x4.trans.shared.b16 {%0,%1,%2,%3}, [%4];"
                 : "=r"(r[0]), "=r"(r[1]), "=r"(r[2]), "=r"(r[3]) : "r"(addr));
}
__device__ __forceinline__ void mma16816(float d[4], const uint32_t a[4],
                                         uint32_t b0, uint32_t b1){
    asm volatile(
        "mma.sync.aligned.m16n8k16.row.col.f32.bf16.bf16.f32 "
        "{%0,%1,%2,%3}, {%4,%5,%6,%7}, {%8,%9}, {%0,%1,%2,%3};"
        : "+f"(d[0]), "+f"(d[1]), "+f"(d[2]), "+f"(d[3])
        : "r"(a[0]), "r"(a[1]), "r"(a[2]), "r"(a[3]), "r"(b0), "r"(b1));
}

// -------- h0 = broadcast struc_emb (+ write catT h-part hi/lo) --------
__global__ void k_init_h(const float* __restrict__ se){
    int j = blockIdx.x*256 + threadIdx.x;     // NH exactly
    int n = j >> 6, hc = j & 63;
    float v = se[j];
    __nv_bfloat16 hi = __float2bfloat16(v);
    __nv_bfloat16 lo = __float2bfloat16(v - __bfloat162float(hi));
    #pragma unroll
    for(int b=0;b<Bq;b++){
        g_h[(size_t)b*NH + j] = v;
        size_t o = (size_t)n*NPAD + b*CHW + 4 + hc;
        g_bh[o] = hi;
        g_bl[o] = lo;
    }
}

// -------- split adj into bf16 hi/lo --------
__global__ void k_split_adj(const float* __restrict__ adj){
    size_t i = (size_t)blockIdx.x*256 + threadIdx.x;   // Nq*Nq exactly
    float v = adj[i];
    __nv_bfloat16 hi = __float2bfloat16(v);
    g_ah[i] = hi;
    g_al[i] = __float2bfloat16(v - __bfloat162float(hi));
}

// -------- split W1|W2 into bf16 hi/lo [80][256], rows>=68 zero --------
__global__ void k_split_w(const float* __restrict__ W1, const float* __restrict__ W2){
    int idx = blockIdx.x*256 + threadIdx.x;   // 80*256 exactly
    int f = idx >> 8, ch = idx & 255;
    float v = 0.f;
    if(f < 68) v = (ch < 192) ? W1[f*192 + ch] : W2[f*64 + ch - 192];
    __nv_bfloat16 hi = __float2bfloat16(v);
    g_wh[idx] = hi;
    g_wl[idx] = __float2bfloat16(v - __bfloat162float(hi));
}

// -------- decoder weight pre-split (permuted col = hc*4+gate) --------
__global__ void k_split_dec(const float* __restrict__ W_ih, const float* __restrict__ W_hh,
                            const float* __restrict__ b_ih, const float* __restrict__ b_hh,
                            const float* __restrict__ D1){
    int idx = blockIdx.x*256 + threadIdx.x;  // 64*256 exactly
    int k = idx >> 8, c = idx & 255;
    int hc = c >> 2, gate = c & 3;
    float vi = W_ih[(gate*64 + hc)*64 + k];
    __nv_bfloat16 hi = __float2bfloat16(vi);
    g_dwih_h[idx] = hi;
    g_dwih_l[idx] = __float2bfloat16(vi - __bfloat162float(hi));
    float vh = W_hh[(gate*64 + hc)*64 + k];
    hi = __float2bfloat16(vh);
    g_dwhh_h[idx] = hi;
    g_dwhh_l[idx] = __float2bfloat16(vh - __bfloat162float(hi));
    if(idx < 64*32){
        float v = D1[idx];
        hi = __float2bfloat16(v);
        g_d1h[idx] = hi;
        g_d1l[idx] = __float2bfloat16(v - __bfloat162float(hi));
    }
    if(idx < 256){
        int g2 = idx & 3, h2 = idx >> 2;
        g_dbb[idx] = b_ih[g2*64 + h2] + b_hh[g2*64 + h2];
    }
}

// -------- catT X-part: cols b*68+f (f<4), per step --------
__global__ void k_catx(const float* __restrict__ X, int t){
    int i = blockIdx.x*256 + threadIdx.x;   // 32*4096 exactly
    int b = i >> 14, f = (i >> 12) & 3, k = i & 4095;
    float v = X[(size_t)((b*Sq + t)*Nq + k)*Fq + f];
    __nv_bfloat16 hi = __float2bfloat16(v);
    size_t o = (size_t)k*NPAD + b*CHW + f;
    g_bh[o] = hi;
    g_bl[o] = __float2bfloat16(v - __bfloat162float(hi));
}

// ===================== HMMA GEMM (encoder diffusion) =====================
#define MSTAGE 24576
#define MA_HI  0
#define MA_LO  8192
#define MB_HI  16384
#define MB_LO  20480

__device__ __forceinline__ void mma_load_stage(uint32_t dbase, int s, int kt,
                                               int m0, int n0, int tid){
    const uint32_t sb = dbase + (uint32_t)s*MSTAGE;
    const int k0 = kt*32;
    #pragma unroll
    for(int it=0; it<4; it++){
        int i = tid + it*256;
        int arr = i >> 9, rem = i & 511;
        int row = rem >> 2, c = rem & 3;
        const __nv_bfloat16* src = (arr ? g_al : g_ah)
            + ((size_t)(m0+row) << 12) + k0 + c*8;
        uint32_t dst = sb + (arr ? MA_LO : MA_HI)
            + (uint32_t)row*64 + (uint32_t)((c ^ ((row>>1)&3))<<4);
        cpasync16(dst, src);
    }
    #pragma unroll
    for(int it=0; it<2; it++){
        int i = tid + it*256;
        int arr = i >> 8, rem = i & 255;
        int row = rem >> 3, c = rem & 7;
        const __nv_bfloat16* src = (arr ? g_bl : g_bh)
            + (size_t)(k0+row)*NPAD + n0 + c*8;
        uint32_t dst = sb + (arr ? MB_LO : MB_HI)
            + (uint32_t)row*128 + (uint32_t)((c ^ (row&7))<<4);
        cpasync16(dst, src);
    }
}

__global__ __launch_bounds__(256,2) void k_mma(){
    extern __shared__ char dyn[];
    const uint32_t dbase = smem_u32(dyn);
    const int tid = threadIdx.x;
    const int lane = tid & 31, wid = tid >> 5;
    const int warp_m = wid & 3, warp_n = wid >> 2;
    const int m0 = blockIdx.x * 128;
    const int n0 = blockIdx.y * 64;
    const int lrow = lane & 15, lhalf = lane >> 4;

    float acc[2][4][4];
    #pragma unroll
    for(int mt=0;mt<2;mt++)
        #pragma unroll
        for(int nt=0;nt<4;nt++)
            #pragma unroll
            for(int q=0;q<4;q++) acc[mt][nt][q] = 0.f;

    mma_load_stage(dbase, 0, 0, m0, n0, tid);
    asm volatile("cp.async.commit_group;" ::: "memory");
    mma_load_stage(dbase, 1, 1, m0, n0, tid);
    asm volatile("cp.async.commit_group;" ::: "memory");

    int s_cur = 0;
    for(int kt=0; kt<128; kt++){
        if(kt < 127){ asm volatile("cp.async.wait_group 1;" ::: "memory"); }
        else        { asm volatile("cp.async.wait_group 0;" ::: "memory"); }
        __syncthreads();

        if(kt + 2 < 128){
            int s2 = s_cur + 2; if(s2 >= 3) s2 -= 3;
            mma_load_stage(dbase, s2, kt+2, m0, n0, tid);
            asm volatile("cp.async.commit_group;" ::: "memory");
        }

        const uint32_t sb = dbase + (uint32_t)s_cur*MSTAGE;
        #pragma unroll
        for(int k16=0; k16<2; k16++){
            uint32_t ah[2][4], al[2][4];
            #pragma unroll
            for(int mt=0; mt<2; mt++){
                int row = warp_m*32 + mt*16 + lrow;
                int c = k16*2 + lhalf;
                uint32_t off = (uint32_t)row*64 + (uint32_t)((c ^ ((row>>1)&3))<<4);
                ldsm4(ah[mt], sb + MA_HI + off);
                ldsm4(al[mt], sb + MA_LO + off);
            }
            uint32_t bh[2][4], bl[2][4];
            #pragma unroll
            for(int nt16=0; nt16<2; nt16++){
                int k = k16*16 + lrow;
                int c = warp_n*4 + nt16*2 + lhalf;
                uint32_t off = (uint32_t)k*128 + (uint32_t)((c ^ (k&7))<<4);
                ldsm4t(bh[nt16], sb + MB_HI + off);
                ldsm4t(bl[nt16], sb + MB_LO + off);
            }
            #pragma unroll
            for(int mt=0; mt<2; mt++)
                #pragma unroll
                for(int nt16=0; nt16<2; nt16++)
                    #pragma unroll
                    for(int h8=0; h8<2; h8++){
                        float* d = acc[mt][nt16*2 + h8];
                        uint32_t b0 = bh[nt16][2*h8], b1 = bh[nt16][2*h8+1];
                        mma16816(d, ah[mt], b0, b1);
                        mma16816(d, ah[mt], bl[nt16][2*h8], bl[nt16][2*h8+1]);
                        mma16816(d, al[mt], b0, b1);
                    }
        }
        s_cur++; if(s_cur == 3) s_cur = 0;
    }

    #pragma unroll
    for(int mt=0; mt<2; mt++){
        #pragma unroll
        for(int nt=0; nt<4; nt++){
            int col = n0 + warp_n*32 + nt*8 + (lane&3)*2;
            if(col < NCOL){
                int r0 = m0 + warp_m*32 + mt*16 + (lane>>2);
                float2 v0; v0.x = acc[mt][nt][0]; v0.y = acc[mt][nt][1];
                float2 v1; v1.x = acc[mt][nt][2]; v1.y = acc[mt][nt][3];
                *(float2*)(g_a + (size_t)r0*NCOL + col)     = v0;
                *(float2*)(g_a + (size_t)(r0+8)*NCOL + col) = v1;
            }
        }
    }
}

// ===================== HMMA gates GEMM + activations =====================
#define GA_ST 88
#define GW_ST 136
#define GSM_AH 0
#define GSM_AL (128*GA_ST*2)
#define GSM_WH (2*128*GA_ST*2)
#define GSM_WL (2*128*GA_ST*2 + 80*GW_ST*2)
#define GSM_BC (2*128*GA_ST*2 + 2*80*GW_ST*2)
#define GSM_TOT (GSM_BC + 128*4)

__global__ __launch_bounds__(256,1) void k_gates_mma(
        const float* __restrict__ b1, const float* __restrict__ b2){
    extern __shared__ char smg[];
    const uint32_t sb = smem_u32(smg);
    __nv_bfloat16* aH = (__nv_bfloat16*)(smg + GSM_AH);
    __nv_bfloat16* aL = (__nv_bfloat16*)(smg + GSM_AL);
    __nv_bfloat16* wH = (__nv_bfloat16*)(smg + GSM_WH);
    __nv_bfloat16* wL = (__nv_bfloat16*)(smg + GSM_WL);
    float* bc = (float*)(smg + GSM_BC);
    const int tid = threadIdx.x, lane = tid & 31, wid = tid >> 5;
    const int warp_m = wid & 3, warp_n = wid >> 2;
    const int m0 = blockIdx.x * 128;
    const int b  = blockIdx.y;
    const int z  = blockIdx.z;
    const int lrow = lane & 15, lhalf = lane >> 4;

    for(int idx=tid; idx<128*GA_ST; idx+=256){
        int i = idx / GA_ST, f = idx - i*GA_ST;
        float v = (f < CHW) ? g_a[(size_t)(m0+i)*NCOL + b*CHW + f] : 0.f;
        __nv_bfloat16 hi = __float2bfloat16(v);
        aH[idx] = hi;
        aL[idx] = __float2bfloat16(v - __bfloat162float(hi));
    }
    for(int idx=tid; idx<80*GW_ST; idx+=256){
        int f = idx / GW_ST, c = idx - f*GW_ST;
        __nv_bfloat16 zero = __float2bfloat16(0.f);
        wH[idx] = (c < 128) ? g_wh[f*256 + z*128 + c] : zero;
        wL[idx] = (c < 128) ? g_wl[f*256 + z*128 + c] : zero;
    }
    if(tid < 128){
        int ch = z*128 + tid;
        bc[tid] = (ch < 192) ? b1[ch] : b2[ch - 192];
    }
    __syncthreads();

    float acc[2][8][4];
    #pragma unroll
    for(int mt=0;mt<2;mt++)
        #pragma unroll
        for(int nt=0;nt<8;nt++)
            #pragma unroll
            for(int q=0;q<4;q++) acc[mt][nt][q] = 0.f;

    #pragma unroll
    for(int k16=0; k16<5; k16++){
        uint32_t ah[2][4], al[2][4];
        #pragma unroll
        for(int mt=0; mt<2; mt++){
            int row = warp_m*32 + mt*16 + lrow;
            uint32_t off = (uint32_t)row*(GA_ST*2) + (uint32_t)(k16*32 + lhalf*16);
            ldsm4(ah[mt], sb + GSM_AH + off);
            ldsm4(al[mt], sb + GSM_AL + off);
        }
        uint32_t bh[4][4], bl[4][4];
        #pragma unroll
        for(int nt16=0; nt16<4; nt16++){
            int k = k16*16 + lrow;
            uint32_t off = (uint32_t)k*(GW_ST*2)
                + (uint32_t)(warp_n*128 + nt16*32 + lhalf*16);
            ldsm4t(bh[nt16], sb + GSM_WH + off);
            ldsm4t(bl[nt16], sb + GSM_WL + off);
        }
        #pragma unroll
        for(int mt=0; mt<2; mt++)
            #pragma unroll
            for(int nt16=0; nt16<4; nt16++)
                #pragma unroll
                for(int h8=0; h8<2; h8++){
                    float* d = acc[mt][nt16*2 + h8];
                    uint32_t b0 = bh[nt16][2*h8], b1v = bh[nt16][2*h8+1];
                    mma16816(d, ah[mt], b0, b1v);
                    mma16816(d, ah[mt], bl[nt16][2*h8], bl[nt16][2*h8+1]);
                    mma16816(d, al[mt], b0, b1v);
                }
    }

    #pragma unroll
    for(int mt=0; mt<2; mt++){
        #pragma unroll
        for(int nt=0; nt<8; nt++){
            int col = warp_n*64 + nt*8 + (lane&3)*2;
            int ch  = z*128 + col;
            float bb0 = bc[col], bb1 = bc[col+1];
            int r0 = m0 + warp_m*32 + mt*16 + (lane>>2);
            #pragma unroll
            for(int hf=0; hf<2; hf++){
                int node = r0 + 8*hf;
                float v0 = acc[mt][nt][2*hf]   + bb0;
                float v1 = acc[mt][nt][2*hf+1] + bb1;
                if(ch < 192){
                    float2 o; o.x = sigf(v0); o.y = sigf(v1);
                    *(float2*)(g_gate + (size_t)b*N3H + (size_t)node*192 + ch) = o;
                }else{
                    float2 o; o.x = tanhf(v0); o.y = tanhf(v1);
                    *(float2*)(g_tconv + (size_t)b*NH + (size_t)node*64 + (ch-192)) = o;
                }
            }
        }
    }
}

// -------- LSTM cell elementwise + write catT h-part for next step --------
__global__ void k_cell(const float* __restrict__ se){
    int idx = blockIdx.x*256 + threadIdx.x;     // Bq*NH exactly
    int b = idx >> 18;
    int j = idx & (NH-1);
    const float* gg = g_gate + (size_t)b*N3H;
    float f = gg[j], i = gg[NH + j], o = gg[2*NH + j];
    float c = f*se[j] + i*g_tconv[idx];
    float h = o * tanhf(c);
    g_h[idx] = h;
    int n = j >> 6, hc = j & 63;
    __nv_bfloat16 hi = __float2bfloat16(h);
    size_t ofs = (size_t)n*NPAD + b*CHW + 4 + hc;
    g_bh[ofs] = hi;
    g_bl[ofs] = __float2bfloat16(h - __bfloat162float(hi));
}

// -------- copy z to output --------
__global__ void k_copy_z(float* __restrict__ out){
    int idx = blockIdx.x*256 + threadIdx.x;     // Bq*NH exactly
    out[idx] = g_h[idx];
}

// ===================== MMA decoder =====================
// 64 rows/block, 8 warps. Per step: gates = XG + h@Whh' (3-term bf16 MMA),
// gate combine via lane-pair shuffles (cols permuted hc*4+gate),
// head = relu(h@D1+bd1)@D2+bd2 via a second small MMA.
#define DW_ST 264
#define DA_ST 72
#define DX_ST 260
#define DD_ST 40
#define DS_WH 0
#define DS_WL (DS_WH + 64*DW_ST*2)
#define DS_AH (DS_WL + 64*DW_ST*2)
#define DS_AL (DS_AH + 64*DA_ST*2)
#define DS_XG (DS_AL + 64*DA_ST*2)
#define DS_D1H (DS_XG + 64*DX_ST*4)
#define DS_D1L (DS_D1H + 64*DD_ST*2)
#define DS_RED (DS_D1L + 64*DD_ST*2)
#define DS_BB  (DS_RED + 64*8*4)
#define DS_B1  (DS_BB + 256*4)
#define DS_D2  (DS_B1 + 32*4)
#define DS_TOT (DS_D2 + 32*4)

__device__ __forceinline__ void dec_gemm_k64(float acc[2][8][4], uint32_t sb,
        int wm, int wn, int lrow, int lhalf){
    #pragma unroll
    for(int k16=0;k16<4;k16++){
        uint32_t ah[2][4], al[2][4];
        #pragma unroll
        for(int mt=0;mt<2;mt++){
            int row = wm*32 + mt*16 + lrow;
            uint32_t off = (uint32_t)row*(DA_ST*2) + (uint32_t)(k16*32 + lhalf*16);
            ldsm4(ah[mt], sb + DS_AH + off);
            ldsm4(al[mt], sb + DS_AL + off);
        }
        uint32_t bh[4][4], bl[4][4];
        #pragma unroll
        for(int nt16=0;nt16<4;nt16++){
            int k = k16*16 + lrow;
            uint32_t off = (uint32_t)k*(DW_ST*2)
                + (uint32_t)(wn*128 + nt16*32 + lhalf*16);
            ldsm4t(bh[nt16], sb + DS_WH + off);
            ldsm4t(bl[nt16], sb + DS_WL + off);
        }
        #pragma unroll
        for(int mt=0;mt<2;mt++)
            #pragma unroll
            for(int nt16=0;nt16<4;nt16++)
                #pragma unroll
                for(int h8=0;h8<2;h8++){
                    float* d = acc[mt][nt16*2 + h8];
                    uint32_t b0 = bh[nt16][2*h8], b1v = bh[nt16][2*h8+1];
                    mma16816(d, ah[mt], b0, b1v);
                    mma16816(d, ah[mt], bl[nt16][2*h8], bl[nt16][2*h8+1]);
                    mma16816(d, al[mt], b0, b1v);
                }
    }
}

__global__ __launch_bounds__(256,1) void k_dec_mma(
        const float* __restrict__ bd1, const float* __restrict__ D2,
        const float* __restrict__ bd2, float* __restrict__ out)
{
    extern __shared__ char smd[];
    const uint32_t sb = smem_u32(smd);
    __nv_bfloat16* WH = (__nv_bfloat16*)(smd + DS_WH);
    __nv_bfloat16* WL = (__nv_bfloat16*)(smd + DS_WL);
    __nv_bfloat16* AH = (__nv_bfloat16*)(smd + DS_AH);
    __nv_bfloat16* AL = (__nv_bfloat16*)(smd + DS_AL);
    float* XG  = (float*)(smd + DS_XG);
    __nv_bfloat16* D1H = (__nv_bfloat16*)(smd + DS_D1H);
    __nv_bfloat16* D1L = (__nv_bfloat16*)(smd + DS_D1L);
    float* RED = (float*)(smd + DS_RED);
    float* BB  = (float*)(smd + DS_BB);
    float* B1S = (float*)(smd + DS_B1);
    float* D2S = (float*)(smd + DS_D2);
    const int tid = threadIdx.x, lane = tid & 31, wid = tid >> 5;
    const int r0 = blockIdx.x * 64;
    const int lrow = lane & 15, lhalf = lane >> 4;
    const int q = lane & 3, rql = lane >> 2;
    const int wm = wid & 1, wn = wid >> 1;     // decoder GEMM layout
    const int hm = wid >> 1, hn = wid & 1;     // head GEMM layout

    // ---- prologue loads ----
    for(int idx=tid; idx<64*64; idx+=256){
        int row = idx >> 6, k = idx & 63;
        float v = g_h[(size_t)(r0+row)*64 + k];
        __nv_bfloat16 hi = __float2bfloat16(v);
        AH[row*DA_ST + k] = hi;
        AL[row*DA_ST + k] = __float2bfloat16(v - __bfloat162float(hi));
    }
    for(int idx=tid; idx<64*256; idx+=256){
        int k = idx >> 8, c = idx & 255;
        WH[k*DW_ST + c] = g_dwih_h[idx];
        WL[k*DW_ST + c] = g_dwih_l[idx];
    }
    for(int idx=tid; idx<64*DD_ST; idx+=256){
        int k = idx / DD_ST, c = idx - k*DD_ST;
        __nv_bfloat16 z16 = __float2bfloat16(0.f);
        D1H[idx] = (c < 32) ? g_d1h[k*32 + c] : z16;
        D1L[idx] = (c < 32) ? g_d1l[k*32 + c] : z16;
    }
    if(tid < 256) BB[tid] = g_dbb[tid];
    if(tid < 32){ B1S[tid] = bd1[tid]; D2S[tid] = D2[tid]; }
    __syncthreads();

    // ---- xg = z @ Wih' + bb ----
    {
        float acc[2][8][4];
        #pragma unroll
        for(int mt=0;mt<2;mt++)
            #pragma unroll
            for(int nt=0;nt<8;nt++){
                int c0 = wn*64 + nt*8 + q*2;
                acc[mt][nt][0] = BB[c0];   acc[mt][nt][1] = BB[c0+1];
                acc[mt][nt][2] = BB[c0];   acc[mt][nt][3] = BB[c0+1];
            }
        dec_gemm_k64(acc, sb, wm, wn, lrow, lhalf);
        #pragma unroll
        for(int mt=0;mt<2;mt++)
            #pragma unroll
            for(int nt=0;nt<8;nt++){
                int r = wm*32 + mt*16 + rql;
                int c0 = wn*64 + nt*8 + q*2;
                XG[r*DX_ST + c0]       = acc[mt][nt][0];
                XG[r*DX_ST + c0+1]     = acc[mt][nt][1];
                XG[(r+8)*DX_ST + c0]   = acc[mt][nt][2];
                XG[(r+8)*DX_ST + c0+1] = acc[mt][nt][3];
            }
    }
    __syncthreads();
    // ---- Whh -> W smem ----
    for(int idx=tid; idx<64*256; idx+=256){
        int k = idx >> 8, c = idx & 255;
        WH[k*DW_ST + c] = g_dwhh_h[idx];
        WL[k*DW_ST + c] = g_dwhh_l[idx];
    }
    __syncthreads();

    float cst[2][8];
    #pragma unroll
    for(int mt=0;mt<2;mt++)
        #pragma unroll
        for(int nt=0;nt<8;nt++) cst[mt][nt] = 0.f;
    const float bd2v = bd2[0];

    for(int s=0; s<Sq; s++){
        // phase 1: acc = XG (+ h@Whh' for s>0)
        float acc[2][8][4];
        #pragma unroll
        for(int mt=0;mt<2;mt++)
            #pragma unroll
            for(int nt=0;nt<8;nt++){
                int r = wm*32 + mt*16 + rql;
                int c0 = wn*64 + nt*8 + q*2;
                acc[mt][nt][0] = XG[r*DX_ST + c0];
                acc[mt][nt][1] = XG[r*DX_ST + c0+1];
                acc[mt][nt][2] = XG[(r+8)*DX_ST + c0];
                acc[mt][nt][3] = XG[(r+8)*DX_ST + c0+1];
            }
        if(s > 0) dec_gemm_k64(acc, sb, wm, wn, lrow, lhalf);
        __syncthreads();

        // phase 2: gates + h writes
        #pragma unroll
        for(int mt=0;mt<2;mt++){
            #pragma unroll
            for(int nt=0;nt<8;nt++){
                float d0 = acc[mt][nt][0], d1 = acc[mt][nt][1];
                float d2 = acc[mt][nt][2], d3 = acc[mt][nt][3];
                float e0 = __shfl_xor_sync(0xffffffffu, d0, 1);
                float e1 = __shfl_xor_sync(0xffffffffu, d1, 1);
                float e2 = __shfl_xor_sync(0xffffffffu, d2, 1);
                float e3 = __shfl_xor_sync(0xffffffffu, d3, 1);
                float iv, fv, gv, ov;
                if((lane & 1) == 0){ iv = d0; fv = d1; gv = e0; ov = e1; }
                else               { iv = e2; fv = e3; gv = d2; ov = d3; }
                float cc = sigf(fv)*cst[mt][nt] + sigf(iv)*tanhf(gv);
                cst[mt][nt] = cc;
                float hh = sigf(ov)*tanhf(cc);
                int row = wm*32 + mt*16 + rql + ((lane & 1) << 3);
                int hc  = wn*16 + nt*2 + (q >> 1);
                __nv_bfloat16 hi = __float2bfloat16(hh);
                AH[row*DA_ST + hc] = hi;
                AL[row*DA_ST + hc] = __float2bfloat16(hh - __bfloat162float(hi));
            }
        }
        __syncthreads();

        // phase 3: head MMA u = h@D1 + bd1
        float u[2][4];
        #pragma unroll
        for(int h8=0;h8<2;h8++){
            int c0 = hn*16 + h8*8 + q*2;
            u[h8][0] = B1S[c0]; u[h8][1] = B1S[c0+1];
            u[h8][2] = B1S[c0]; u[h8][3] = B1S[c0+1];
        }
        #pragma unroll
        for(int k16=0;k16<4;k16++){
            uint32_t a2h[4], a2l[4];
            {
                int row = hm*16 + lrow;
                uint32_t off = (uint32_t)row*(DA_ST*2) + (uint32_t)(k16*32 + lhalf*16);
                ldsm4(a2h, sb + DS_AH + off);
                ldsm4(a2l, sb + DS_AL + off);
            }
            uint32_t dh[4], dl[4];
            {
                int k = k16*16 + lrow;
                uint32_t off = (uint32_t)k*(DD_ST*2) + (uint32_t)(hn*32 + lhalf*16);
                ldsm4t(dh, sb + DS_D1H + off);
                ldsm4t(dl, sb + DS_D1L + off);
            }
            #pragma unroll
            for(int h8=0;h8<2;h8++){
                mma16816(u[h8], a2h, dh[2*h8], dh[2*h8+1]);
                mma16816(u[h8], a2h, dl[2*h8], dl[2*h8+1]);
                mma16816(u[h8], a2l, dh[2*h8], dh[2*h8+1]);
            }
        }
        float pr = 0.f, pr8 = 0.f;
        #pragma unroll
        for(int h8=0;h8<2;h8++){
            int c0 = hn*16 + h8*8 + q*2;
            pr  += fmaxf(u[h8][0],0.f)*D2S[c0] + fmaxf(u[h8][1],0.f)*D2S[c0+1];
            pr8 += fmaxf(u[h8][2],0.f)*D2S[c0] + fmaxf(u[h8][3],0.f)*D2S[c0+1];
        }
        int hr = hm*16 + rql;
        RED[hr*8 + hn*4 + q]     = pr;
        RED[(hr+8)*8 + hn*4 + q] = pr8;
        __syncthreads();
        if(tid < 64){
            float ssum = bd2v;
            #pragma unroll
            for(int e=0;e<8;e++) ssum += RED[tid*8 + e];
            out[ZOUT + (size_t)(r0 + tid)*Sq + s] = ssum;
        }
    }
}

// ------------------------------------------------------------------
extern "C" void kernel_launch(void* const* d_in, const int* in_sizes, int n_in,
                              void* d_out, int out_size)
{
    const float* X    = (const float*)d_in[0];
    const float* adj  = (const float*)d_in[1];
    const float* se   = (const float*)d_in[2];
    const float* W1   = (const float*)d_in[3];
    const float* b1   = (const float*)d_in[4];
    const float* W2   = (const float*)d_in[5];
    const float* b2   = (const float*)d_in[6];
    const float* W_ih = (const float*)d_in[7];
    const float* W_hh = (const float*)d_in[8];
    const float* b_ih = (const float*)d_in[9];
    const float* b_hh = (const float*)d_in[10];
    const float* D1   = (const float*)d_in[11];
    const float* bd1  = (const float*)d_in[12];
    const float* D2   = (const float*)d_in[13];
    const float* bd2  = (const float*)d_in[14];
    float* out = (float*)d_out;

    const int smem_mma = 3*MSTAGE;                                   // 73728
    cudaFuncSetAttribute(k_mma,       cudaFuncAttributeMaxDynamicSharedMemorySize, smem_mma);
    cudaFuncSetAttribute(k_gates_mma, cudaFuncAttributeMaxDynamicSharedMemorySize, GSM_TOT);
    cudaFuncSetAttribute(k_dec_mma,   cudaFuncAttributeMaxDynamicSharedMemorySize, DS_TOT);

    k_split_adj<<<(int)((Nq*(size_t)Nq)/256), 256>>>(adj);
    k_split_w<<<80, 256>>>(W1, W2);
    k_split_dec<<<64, 256>>>(W_ih, W_hh, b_ih, b_hh, D1);
    k_init_h<<<NH/256, 256>>>(se);
    for(int t=0; t<Sq; t++){
        k_catx<<<(32*4096)/256, 256>>>(X, t);
        k_mma <<<dim3(Nq/128, 9), 256, smem_mma>>>();
        k_gates_mma<<<dim3(Nq/128, Bq, 2), 256, GSM_TOT>>>(b1, b2);
        k_cell <<<(Bq*NH)/256, 256>>>(se);
    }
    k_copy_z<<<(Bq*NH)/256, 256>>>(out);
    k_dec_mma<<<(Bq*Nq)/64, 256, DS_TOT>>>(bd1, D2, bd2, out);
}